// round 12
// baseline (speedup 1.0000x reference)
#include <cuda_runtime.h>
#include <cstdint>

#define L 4096
#define NB 4

// Scratch (no device allocation allowed in kernel_launch)
__device__ float g_rows[NB * L];   // g_rows[c*L + x] = base_table[seq[x]*4 + c]

// ---------------------------------------------------------------------------
// Prep: 32 blocks x 128 threads, decode seq -> g_rows once. Consumed ONLY by
// fill's c>=4 blocks. Triggers programmatic completion after its stores.
// dtype detection per block: 64 odd-word samples within the first 2048
// elements (int64 values 0..3 -> all zero; int32 -> ~surely nonzero).
// ---------------------------------------------------------------------------
__global__ void prep_kernel(const int* __restrict__ w,
                            const float* __restrict__ tab) {
    __shared__ int s_nonzero_odd;
    const int tid = threadIdx.x;
    const int b   = blockIdx.x;

    if (tid == 0) s_nonzero_odd = 0;
    __syncthreads();

    if (tid < 64) {
        const int k = b * 64 + tid;            // k in [0, 2048)
        if (w[2 * k + 1] != 0) atomicOr(&s_nonzero_odd, 1);
    }
    __syncthreads();
    const int sh = (s_nonzero_odd == 0) ? 1 : 0;

    const int i = b * 128 + tid;               // element index
    const int s = w[i << sh];
    #pragma unroll
    for (int c = 0; c < NB; c++) {
        g_rows[c * L + i] = tab[s * NB + c];
    }

    cudaTriggerProgrammaticLaunchCompletion();
}

// ---------------------------------------------------------------------------
// Fill: 2048 blocks x 256 threads, 64 STG.128/thread, contiguous 256 KB per
// block (the proven 79.4us store structure).
//
// Blocks [0,1024): channels 4..7 — need g_rows (per-column data); they
//   grid-dep-sync on prep, then run the unchanged store loop.
// Blocks [1024,2048): channels 0..3 — need only 16 broadcast scalars; they
//   decode inline (warp-ballot dtype detection, both-width candidate loads
//   issued up front) and NEVER wait on prep -> DRAM busy from t=0.
// ---------------------------------------------------------------------------
__global__ void __launch_bounds__(256, 8)
fill_kernel(const int* __restrict__ w,
            const float* __restrict__ tab,
            float4* __restrict__ out) {
    const int tid = threadIdx.x;
    const unsigned b = blockIdx.x;

    if (b < 1024u) {
        const int c2    = b >> 8;              // 0..3 (channel - 4)
        const int slice = b & 255;             // 16-row slice within channel

        float4* p = out
                  + (((size_t)(4 + c2) << 12) + ((size_t)slice << 4)) * 1024
                  + tid;

        cudaGridDependencySynchronize();       // wait for prep's g_rows writes

        const float4* row = (const float4*)&g_rows[c2 << 12];
        const float4 v0 = row[          tid];
        const float4 v1 = row[256     + tid];
        const float4 v2 = row[512     + tid];
        const float4 v3 = row[768     + tid];

        #pragma unroll 4
        for (int r = 0; r < 16; r++) {
            p[0]   = v0;
            p[256] = v1;
            p[512] = v2;
            p[768] = v3;
            p += 1024;                         // next consecutive row
        }
    } else {
        // ---- channels 0..3: fully independent of prep ----
        const unsigned row0 = (b - 1024u) << 4;      // 16 consecutive rows
        const int c  = (int)(row0 >> 12);            // channel 0..3
        const int i0 = (int)(row0 & 4095);
        const int lane = tid & 31;

        // Issue everything up front, no dependent chains:
        //  - detection sample (coalesced): odd word of element `lane`
        //  - both-width candidate seq words (warp-uniform)
        //  - 4 table values
        const int det = w[2 * lane + 1];
        int s32[16], s64[16];
        #pragma unroll
        for (int r = 0; r < 16; r++) {
            s32[r] = w[i0 + r];
            s64[r] = w[(i0 + r) << 1];
        }
        const float t0 = __ldg(&tab[ 0 + c]);
        const float t1 = __ldg(&tab[ 4 + c]);
        const float t2 = __ldg(&tab[ 8 + c]);
        const float t3 = __ldg(&tab[12 + c]);

        // int64 (values 0..3) -> all odd words zero; int32 -> some nonzero.
        const bool is64 = !__any_sync(0xFFFFFFFFu, det != 0);

        float4* o = out + (size_t)row0 * 1024 + tid;
        #pragma unroll 4
        for (int r = 0; r < 16; r++) {
            const int si = is64 ? s64[r] : s32[r];
            const float f = (si == 0) ? t0 : (si == 1) ? t1 : (si == 2) ? t2 : t3;
            const float4 v = make_float4(f, f, f, f);
            o[0]   = v;
            o[256] = v;
            o[512] = v;
            o[768] = v;
            o += 1024;
        }
    }
}

extern "C" void kernel_launch(void* const* d_in, const int* in_sizes, int n_in,
                              void* d_out, int out_size) {
    const int*   seq        = (const int*)d_in[0];
    const float* base_table = (const float*)d_in[1];

    prep_kernel<<<32, 128>>>(seq, base_table);

    // PDL: fill launches while prep is in flight; only its c>=4 blocks wait.
    cudaLaunchConfig_t cfg = {};
    cfg.gridDim  = dim3(2048);
    cfg.blockDim = dim3(256);
    cudaLaunchAttribute attr[1];
    attr[0].id = cudaLaunchAttributeProgrammaticStreamSerialization;
    attr[0].val.programmaticStreamSerializationAllowed = 1;
    cfg.attrs    = attr;
    cfg.numAttrs = 1;
    cudaLaunchKernelEx(&cfg, fill_kernel, seq, base_table, (float4*)d_out);
}

// round 14
// speedup vs baseline: 1.0747x; 1.0747x over previous
#include <cuda_runtime.h>
#include <cstdint>

#define L 4096
#define NB 4

// Scratch (no device allocation allowed in kernel_launch)
__device__ float g_rows[NB * L];   // g_rows[c*L + x] = base_table[seq[x]*4 + c]

// ---------------------------------------------------------------------------
// Prep (unchanged from R11): 32 blocks x 128 threads, decode seq -> g_rows.
// dtype detection per block: 64 odd-word samples within the first 2048
// elements (int64 values 0..3 -> all zero; int32 -> ~surely nonzero).
// ---------------------------------------------------------------------------
__global__ void prep_kernel(const int* __restrict__ w,
                            const float* __restrict__ tab) {
    __shared__ int s_nonzero_odd;
    const int tid = threadIdx.x;
    const int b   = blockIdx.x;

    if (tid == 0) s_nonzero_odd = 0;
    __syncthreads();

    if (tid < 64) {
        const int k = b * 64 + tid;            // k in [0, 2048)
        if (w[2 * k + 1] != 0) atomicOr(&s_nonzero_odd, 1);
    }
    __syncthreads();
    const int sh = (s_nonzero_odd == 0) ? 1 : 0;

    const int i = b * 128 + tid;               // element index
    const int s = w[i << sh];
    #pragma unroll
    for (int c = 0; c < NB; c++) {
        g_rows[c * L + i] = tab[s * NB + c];
    }

    cudaTriggerProgrammaticLaunchCompletion();
}

// ---------------------------------------------------------------------------
// Fill (R11 body, ONLY change: stores use __stcs streaming/evict-first hint):
// 2048 blocks x 256 threads, 64 STG.128/thread, contiguous 256 KB per block.
// ---------------------------------------------------------------------------
__global__ void __launch_bounds__(256, 8)
fill_kernel(float4* __restrict__ out) {
    const int tid = threadIdx.x;
    const unsigned b = blockIdx.x;

    if (b < 1024u) {
        const int c2    = b >> 8;              // 0..3 (channel - 4)
        const int slice = b & 255;             // 16-row slice within channel

        float4* p = out
                  + (((size_t)(4 + c2) << 12) + ((size_t)slice << 4)) * 1024
                  + tid;

        cudaGridDependencySynchronize();       // wait for prep's g_rows writes

        const float4* row = (const float4*)&g_rows[c2 << 12];
        const float4 v0 = row[          tid];
        const float4 v1 = row[256     + tid];
        const float4 v2 = row[512     + tid];
        const float4 v3 = row[768     + tid];

        #pragma unroll 4
        for (int r = 0; r < 16; r++) {
            __stcs(p,       v0);
            __stcs(p + 256, v1);
            __stcs(p + 512, v2);
            __stcs(p + 768, v3);
            p += 1024;                         // next consecutive row
        }
    } else {
        const unsigned row0 = (b - 1024u) << 4;   // 16 rows, global rows 0..16383
        float4* o = out + (size_t)row0 * 1024 + tid;

        cudaGridDependencySynchronize();       // wait for prep's g_rows writes

        #pragma unroll 1
        for (int r = 0; r < 16; r++) {
            const float s = g_rows[row0 + r];     // row == c*4096 + i
            const float4 v = make_float4(s, s, s, s);
            __stcs(o,       v);
            __stcs(o + 256, v);
            __stcs(o + 512, v);
            __stcs(o + 768, v);
            o += 1024;
        }
    }
}

extern "C" void kernel_launch(void* const* d_in, const int* in_sizes, int n_in,
                              void* d_out, int out_size) {
    const int*   seq        = (const int*)d_in[0];
    const float* base_table = (const float*)d_in[1];

    prep_kernel<<<32, 128>>>(seq, base_table);

    // PDL: fill launches while prep is in flight (neutral but harmless).
    cudaLaunchConfig_t cfg = {};
    cfg.gridDim  = dim3(2048);
    cfg.blockDim = dim3(256);
    cudaLaunchAttribute attr[1];
    attr[0].id = cudaLaunchAttributeProgrammaticStreamSerialization;
    attr[0].val.programmaticStreamSerializationAllowed = 1;
    cfg.attrs    = attr;
    cfg.numAttrs = 1;
    cudaLaunchKernelEx(&cfg, fill_kernel, (float4*)d_out);
}